// round 9
// baseline (speedup 1.0000x reference)
#include <cuda_runtime.h>
#include <math.h>
#include <stdint.h>

#define MARGIN            0.3f
#define CLST_SCALE        0.8f
#define SEP_SCALE         0.08f
#define DIV_SCALE         0.01f
#define CONTRASTIVE_SCALE 0.1f

#define MAXC 1024
#define MAXD 1024
#define MAXR 32
#define TPB  128    // 4 warps per block

struct Scratch {
    float cls_n[MAXC];
    float cls_sum[MAXC];
    float sep_sum[MAXC];
    float svec[MAXD];
    float div_sum;
    float ndv;
    float diag;
    unsigned int counter;
};
__device__ Scratch g;

__device__ __forceinline__ float inff() { return __int_as_float(0x7f800000); }

__global__ void __launch_bounds__(TPB, 10)
fused_kernel(const float* __restrict__ sims,
             const int*   __restrict__ labels,
             const float* __restrict__ protos,
             const int*   __restrict__ pidx,
             const unsigned char* __restrict__ mask,
             float* __restrict__ out,
             int B, int C, int P, int T, int D, int NMIN, int fast_ok) {
    const int tid  = threadIdx.x;
    const int warp = tid >> 5, lane = tid & 31;
    const int nwarp = TPB >> 5;

    if ((int)blockIdx.x < C) {
        // =================== proto block for class c =======================
        int bad = 0;
        {
            const int* mi = (const int*)mask;
            const int n = T >> 2;
            for (int i = tid; i < n; i += TPB) {
                int v = mi[i];
                bad |= (v != 0 && v != 1);
            }
        }
        const int byte_mode = __syncthreads_or(bad);

        __shared__ float s_inv[MAXR];
        __shared__ float s_rn2[MAXR];
        __shared__ int   s_rvalid[MAXR];
        __shared__ float s_pair;

        const int c = blockIdx.x;
        int rs = pidx[2 * c];
        int re = (c + 1 < C) ? pidx[2 * (c + 1)] : T;
        if (re > T) re = T;
        if (rs < 0) rs = 0;
        int nr = re - rs;
        if (nr > MAXR) nr = MAXR;
        if (nr < 0) nr = 0;

        if (tid == 0) s_pair = 0.f;
        const bool d4ok = ((D & 3) == 0);
        const int  D4   = D >> 2;
        const float4* p4 = (const float4*)protos;

        for (int r = warp; r < nr; r += nwarp) {
            float ss = 0.f;
            if (d4ok) {
                const float4* src = p4 + (size_t)(rs + r) * D4;
                for (int d = lane; d < D4; d += 32) {
                    float4 x = src[d];
                    ss += x.x * x.x + x.y * x.y + x.z * x.z + x.w * x.w;
                }
            } else {
                const float* src = protos + (size_t)(rs + r) * D;
                for (int d = lane; d < D; d += 32) { float v = src[d]; ss += v * v; }
            }
            #pragma unroll
            for (int o = 16; o; o >>= 1) ss += __shfl_xor_sync(0xFFFFFFFFu, ss, o);
            float inv = 1.0f / fmaxf(sqrtf(ss), 1e-12f);
            if (lane == 0) {
                s_inv[r] = inv;
                s_rn2[r] = ss * inv * inv;
                int t = rs + r;
                int v = byte_mode ? (int)mask[t] : ((const int*)mask)[t];
                s_rvalid[r] = (v != 0);
            }
        }
        __syncthreads();

        if (d4ok) {
            for (int d = tid; d < D4; d += TPB) {
                float4 acc = make_float4(0.f, 0.f, 0.f, 0.f);
                for (int r = 0; r < nr; r++) {
                    if (s_rvalid[r]) {
                        float4 x = p4[(size_t)(rs + r) * D4 + d];
                        float iv = s_inv[r];
                        acc.x += x.x * iv; acc.y += x.y * iv;
                        acc.z += x.z * iv; acc.w += x.w * iv;
                    }
                }
                atomicAdd(&g.svec[4 * d + 0], acc.x);
                atomicAdd(&g.svec[4 * d + 1], acc.y);
                atomicAdd(&g.svec[4 * d + 2], acc.z);
                atomicAdd(&g.svec[4 * d + 3], acc.w);
            }
        } else {
            for (int d = tid; d < D; d += TPB) {
                float s = 0.f;
                for (int r = 0; r < nr; r++)
                    if (s_rvalid[r])
                        s += protos[(size_t)(rs + r) * D + d] * s_inv[r];
                atomicAdd(&g.svec[d], s);
            }
        }
        if (tid == 0) {
            float ds = 0.f;
            for (int r = 0; r < nr; r++) if (s_rvalid[r]) ds += s_rn2[r];
            atomicAdd(&g.diag, ds);
        }

        const int npr = nr * (nr - 1) / 2;
        float local = 0.f;
        for (int k = warp; k < npr; k += nwarp) {
            int i = 0, rem = k;
            while (rem >= nr - 1 - i) { rem -= nr - 1 - i; i++; }
            int j = i + 1 + rem;
            float dot = 0.f;
            if (d4ok) {
                const float4* ri = p4 + (size_t)(rs + i) * D4;
                const float4* rj = p4 + (size_t)(rs + j) * D4;
                for (int d = lane; d < D4; d += 32) {
                    float4 a = ri[d], b = rj[d];
                    dot += a.x * b.x + a.y * b.y + a.z * b.z + a.w * b.w;
                }
            } else {
                const float* ri = protos + (size_t)(rs + i) * D;
                const float* rj = protos + (size_t)(rs + j) * D;
                for (int d = lane; d < D; d += 32) dot += ri[d] * rj[d];
            }
            #pragma unroll
            for (int o = 16; o; o >>= 1) dot += __shfl_xor_sync(0xFFFFFFFFu, dot, o);
            if (lane == 0)
                local += 2.0f * fmaxf(dot * s_inv[i] * s_inv[j] - 0.5f, 0.f);
        }
        if (lane == 0 && local != 0.f) atomicAdd(&s_pair, local);
        __syncthreads();

        if (tid == 0) {
            int cnt = pidx[2 * c + 1] - pidx[2 * c];
            if (cnt > 1) {
                float npf = (float)cnt * (float)(cnt - 1);
                atomicAdd(&g.div_sum, s_pair / fmaxf(npf, 1.0f));
                atomicAdd(&g.ndv, 1.0f);
            }
        }
        __syncthreads();
    } else {
        // =================== streaming min warps (lean, no SW pipeline) ====
        const int CP = C * P;
        const int gw = ((int)blockIdx.x - C) * nwarp + warp;
        const int stride = NMIN * nwarp;

        // device-side check: fast path needs every class count >= P
        int okf = 1;
        for (int c = tid; c < C; c += TPB)
            okf &= ((pidx[2 * c + 1] - pidx[2 * c]) >= P);
        okf = __syncthreads_and(okf) & fast_ok;

        if (okf) {
            const int n4 = CP >> 2;
            const float NI = -inff();
            for (int b = gw; b < B; b += stride) {
                const float4* s4 = (const float4*)(sims + (size_t)b * CP);
                const int lbl = labels[b];

                // 8 independent LDG.128 -> immediate per-vector max
                float m[8];
                #pragma unroll
                for (int k = 0; k < 8; k++) {
                    int vi = lane + 32 * k;
                    float4 x = make_float4(NI, NI, NI, NI);
                    if (vi < n4) x = s4[vi];
                    m[k] = fmaxf(fmaxf(x.x, x.y), fmaxf(x.z, x.w));
                }

                const int lo = lbl * P, hi = lo + P;
                const int viL = lo >> 2, viH = (hi - 1) >> 2;
                float oth = NI;
                #pragma unroll
                for (int k = 0; k < 8; k++) {
                    int vi = lane + 32 * k;
                    if (vi < viL || vi > viH) oth = fmaxf(oth, m[k]);
                }

                // boundary region [4*viL, 4*viL+16): lanes 0..15, L1 hits
                float own = NI;
                const int bidx = 4 * viL + lane;
                if (lane < 16 && bidx < CP) {
                    float bv = sims[(size_t)b * CP + bidx];
                    if (bidx >= lo && bidx < hi) own = bv;
                    else if (bidx <= 4 * viH + 3) oth = fmaxf(oth, bv);
                }

                #pragma unroll
                for (int o = 16; o; o >>= 1) {
                    own = fmaxf(own, __shfl_xor_sync(0xFFFFFFFFu, own, o));
                    oth = fmaxf(oth, __shfl_xor_sync(0xFFFFFFFFu, oth, o));
                }
                if (lane == 0) {
                    float ownd = 1.0f - own;
                    float sep  = fmaxf(MARGIN - (1.0f - oth), 0.0f);
                    atomicAdd(&g.cls_n[lbl],   1.0f);
                    atomicAdd(&g.cls_sum[lbl], ownd);
                    atomicAdd(&g.sep_sum[lbl], sep);
                }
            }
        } else {
            // general fallback: per-class scalar walk straight from global
            for (int b = gw; b < B; b += stride) {
                const float* src = sims + (size_t)b * CP;
                const int lbl = labels[b];
                float ownmax = -inff(), othermax = -inff();
                for (int c = lane; c < C; c += 32) {
                    int cnt = pidx[2 * c + 1] - pidx[2 * c];
                    if (cnt > P) cnt = P;
                    float m = -inff();
                    const float* pr = src + c * P;
                    for (int p = 0; p < cnt; p++) m = fmaxf(m, pr[p]);
                    if (c == lbl) ownmax = m;
                    else          othermax = fmaxf(othermax, m);
                }
                #pragma unroll
                for (int o = 16; o; o >>= 1) {
                    ownmax   = fmaxf(ownmax,   __shfl_xor_sync(0xFFFFFFFFu, ownmax,   o));
                    othermax = fmaxf(othermax, __shfl_xor_sync(0xFFFFFFFFu, othermax, o));
                }
                if (lane == 0) {
                    float own   = 1.0f - ownmax;
                    float other = 1.0f - othermax;
                    float sep   = fmaxf(MARGIN - other, 0.0f);
                    atomicAdd(&g.cls_n[lbl],   1.0f);
                    atomicAdd(&g.cls_sum[lbl], own);
                    atomicAdd(&g.sep_sum[lbl], sep);
                }
            }
        }
        __syncthreads();
    }

    // =================== last-block finalize ===============================
    __threadfence();
    __shared__ unsigned int s_ord;
    if (tid == 0) s_ord = atomicAdd(&g.counter, 1u);
    __syncthreads();
    if (s_ord != (unsigned)(C + NMIN - 1)) return;
    __threadfence();

    int bad2 = 0;
    {
        const int* mi = (const int*)mask;
        const int n = T >> 2;
        for (int i = tid; i < n; i += TPB) {
            int v = mi[i];
            bad2 |= (v != 0 && v != 1);
        }
    }
    const int byte_mode = __syncthreads_or(bad2);

    __shared__ float red[TPB];
    float ca = 0.f, sa = 0.f, nv = 0.f;
    for (int c = tid; c < C; c += TPB) {
        float n = g.cls_n[c];
        if (n > 0.f) {
            nv += 1.f;
            float nm = fmaxf(n, 1.f);
            ca += (1.0f / sqrtf(n + 1e-6f)) * (g.cls_sum[c] / nm);
            sa += g.sep_sum[c] / nm;
        }
    }
    float sn = 0.f;
    for (int d = tid; d < D; d += TPB) { float v = g.svec[d]; sn += v * v; }
    float vc = 0.f;
    for (int t = tid; t < T; t += TPB) {
        int v = byte_mode ? (int)mask[t] : ((const int*)mask)[t];
        vc += (v != 0) ? 1.f : 0.f;
    }

    float vals[5] = {ca, sa, nv, sn, vc};
    #pragma unroll
    for (int k = 0; k < 5; k++) {
        red[tid] = vals[k];
        __syncthreads();
        for (int s = TPB >> 1; s; s >>= 1) {
            if (tid < s) red[tid] += red[tid + s];
            __syncthreads();
        }
        vals[k] = red[0];
        __syncthreads();
    }

    if (tid == 0) {
        float nvalid  = fmaxf(vals[2], 1.f);
        float cluster = vals[0] / nvalid * CLST_SCALE;
        float sep     = vals[1] / nvalid * SEP_SCALE;
        float divl    = g.div_sum / fmaxf(g.ndv, 1.f) * DIV_SCALE;
        float V       = vals[4];
        float nvp     = fmaxf(V * V - V, 1.f);
        float contr   = (vals[3] - g.diag) / nvp * CONTRASTIVE_SCALE;
        out[0] = cluster;
        out[1] = sep;
        out[2] = divl;
        out[3] = contr;
        out[4] = cluster + sep + divl + contr;
    }
}

extern "C" void kernel_launch(void* const* d_in, const int* in_sizes, int n_in,
                              void* d_out, int out_size) {
    const float* sims   = (const float*)d_in[0];
    const int*   labels = (const int*)  d_in[1];
    const float* protos = (const float*)d_in[2];
    const int*   pidx   = (const int*)  d_in[3];
    const unsigned char* mask = (const unsigned char*)d_in[4];

    const int B = in_sizes[1];
    const int C = in_sizes[3] / 2;
    const int T = in_sizes[4];
    const int D = in_sizes[2] / T;
    const int P = in_sizes[0] / (B * C);
    float* out = (float*)d_out;

    // Opportunistic L2 persistence window for the big streaming input.
    // Harmless if rejected (error ignored); must NOT touch device limits.
    {
        cudaStreamAttrValue v = {};
        v.accessPolicyWindow.base_ptr  = (void*)sims;
        size_t bytes = (size_t)in_sizes[0] * sizeof(float);
        if (bytes > (size_t)100 * 1024 * 1024) bytes = (size_t)100 * 1024 * 1024;
        v.accessPolicyWindow.num_bytes = bytes;
        v.accessPolicyWindow.hitRatio  = 1.0f;
        v.accessPolicyWindow.hitProp   = cudaAccessPropertyPersisting;
        v.accessPolicyWindow.missProp  = cudaAccessPropertyStreaming;
        (void)cudaStreamSetAttribute((cudaStream_t)0,
                                     cudaStreamAttributeAccessPolicyWindow, &v);
        (void)cudaGetLastError();   // swallow any rejection
    }

    void* gp = nullptr;
    cudaGetSymbolAddress(&gp, g);
    cudaMemsetAsync(gp, 0, sizeof(Scratch), 0);

    const int CP = C * P;
    // fast path: vectorizable row fitting 8 float4/lane, window fits 16 lanes
    const int fast_ok = (((CP & 3) == 0) && (CP <= 1024) && (P <= 13)) ? 1 : 0;

    // 1024 min blocks -> 4096 warps -> exactly B/4096 rows per warp for B=16K
    const int NMIN = 1024;
    fused_kernel<<<C + NMIN, TPB, 0>>>(sims, labels, protos, pidx, mask,
                                       out, B, C, P, T, D, NMIN, fast_ok);
}

// round 10
// speedup vs baseline: 1.0791x; 1.0791x over previous
#include <cuda_runtime.h>
#include <math.h>
#include <stdint.h>

#define MARGIN            0.3f
#define CLST_SCALE        0.8f
#define SEP_SCALE         0.08f
#define DIV_SCALE         0.01f
#define CONTRASTIVE_SCALE 0.1f

#define MAXC 1024
#define MAXD 1024
#define MAXR 32
#define TPB  128    // 4 warps per block
#define SPN_ROWS 10
#define SPN_D4   64     // 256 floats / 4

struct Scratch {
    float cls_n[MAXC];
    float cls_sum[MAXC];
    float sep_sum[MAXC];
    float svec[MAXD];
    float div_sum;
    float ndv;
    float diag;
    unsigned int counter;
};
__device__ Scratch g;

__device__ __forceinline__ float inff() { return __int_as_float(0x7f800000); }

__global__ void __launch_bounds__(TPB, 10)
fused_kernel(const float* __restrict__ sims,
             const int*   __restrict__ labels,
             const float* __restrict__ protos,
             const int*   __restrict__ pidx,
             const unsigned char* __restrict__ mask,
             float* __restrict__ out,
             int B, int C, int P, int T, int D, int NMIN, int fast_ok) {
    const int tid  = threadIdx.x;
    const int warp = tid >> 5, lane = tid & 31;
    const int nwarp = TPB >> 5;

    // static smem proto tile: 10 KB; at 10 blocks/SM = 100 KB < 228 KB, so it
    // does not limit occupancy.
    __shared__ float4 spn[SPN_ROWS * SPN_D4];

    if ((int)blockIdx.x < C) {
        // =================== proto block for class c =======================
        int bad = 0;
        {
            const int* mi = (const int*)mask;
            const int n = T >> 2;
            for (int i = tid; i < n; i += TPB) {
                int v = mi[i];
                bad |= (v != 0 && v != 1);
            }
        }
        const int byte_mode = __syncthreads_or(bad);

        __shared__ float s_inv[MAXR];
        __shared__ float s_rn2[MAXR];
        __shared__ int   s_rvalid[MAXR];
        __shared__ float s_pair;

        const int c = blockIdx.x;
        int rs = pidx[2 * c];
        int re = (c + 1 < C) ? pidx[2 * (c + 1)] : T;
        if (re > T) re = T;
        if (rs < 0) rs = 0;
        int nr = re - rs;
        if (nr > MAXR) nr = MAXR;
        if (nr < 0) nr = 0;

        if (tid == 0) s_pair = 0.f;
        const bool d4ok = ((D & 3) == 0);
        const int  D4   = D >> 2;
        const float4* p4 = (const float4*)protos;
        const bool smok = d4ok && (nr <= SPN_ROWS) && (D4 <= SPN_D4);

        if (smok) {
            // stage class tile into smem (coalesced float4)
            const int nv = nr * D4;
            for (int i = tid; i < nv; i += TPB) {
                int r = i / D4, d = i % D4;
                spn[r * SPN_D4 + d] = p4[(size_t)(rs + r) * D4 + d];
            }
            __syncthreads();

            for (int r = warp; r < nr; r += nwarp) {
                float ss = 0.f;
                for (int d = lane; d < D4; d += 32) {
                    float4 x = spn[r * SPN_D4 + d];
                    ss += x.x * x.x + x.y * x.y + x.z * x.z + x.w * x.w;
                }
                #pragma unroll
                for (int o = 16; o; o >>= 1) ss += __shfl_xor_sync(0xFFFFFFFFu, ss, o);
                float inv = 1.0f / fmaxf(sqrtf(ss), 1e-12f);
                if (lane == 0) {
                    s_inv[r] = inv;
                    s_rn2[r] = ss * inv * inv;
                    int t = rs + r;
                    int v = byte_mode ? (int)mask[t] : ((const int*)mask)[t];
                    s_rvalid[r] = (v != 0);
                }
            }
            __syncthreads();

            for (int d = tid; d < D4; d += TPB) {
                float4 acc = make_float4(0.f, 0.f, 0.f, 0.f);
                for (int r = 0; r < nr; r++) {
                    if (s_rvalid[r]) {
                        float4 x = spn[r * SPN_D4 + d];
                        float iv = s_inv[r];
                        acc.x += x.x * iv; acc.y += x.y * iv;
                        acc.z += x.z * iv; acc.w += x.w * iv;
                    }
                }
                atomicAdd(&g.svec[4 * d + 0], acc.x);
                atomicAdd(&g.svec[4 * d + 1], acc.y);
                atomicAdd(&g.svec[4 * d + 2], acc.z);
                atomicAdd(&g.svec[4 * d + 3], acc.w);
            }
            if (tid == 0) {
                float ds = 0.f;
                for (int r = 0; r < nr; r++) if (s_rvalid[r]) ds += s_rn2[r];
                atomicAdd(&g.diag, ds);
            }

            const int npr = nr * (nr - 1) / 2;
            float local = 0.f;
            for (int k = warp; k < npr; k += nwarp) {
                int i = 0, rem = k;
                while (rem >= nr - 1 - i) { rem -= nr - 1 - i; i++; }
                int j = i + 1 + rem;
                float dot = 0.f;
                for (int d = lane; d < D4; d += 32) {
                    float4 a = spn[i * SPN_D4 + d], b = spn[j * SPN_D4 + d];
                    dot += a.x * b.x + a.y * b.y + a.z * b.z + a.w * b.w;
                }
                #pragma unroll
                for (int o = 16; o; o >>= 1) dot += __shfl_xor_sync(0xFFFFFFFFu, dot, o);
                if (lane == 0)
                    local += 2.0f * fmaxf(dot * s_inv[i] * s_inv[j] - 0.5f, 0.f);
            }
            if (lane == 0 && local != 0.f) atomicAdd(&s_pair, local);
            __syncthreads();
        } else {
            // general path straight from global (L2-resident protos)
            for (int r = warp; r < nr; r += nwarp) {
                float ss = 0.f;
                const float* src = protos + (size_t)(rs + r) * D;
                for (int d = lane; d < D; d += 32) { float v = src[d]; ss += v * v; }
                #pragma unroll
                for (int o = 16; o; o >>= 1) ss += __shfl_xor_sync(0xFFFFFFFFu, ss, o);
                float inv = 1.0f / fmaxf(sqrtf(ss), 1e-12f);
                if (lane == 0) {
                    s_inv[r] = inv;
                    s_rn2[r] = ss * inv * inv;
                    int t = rs + r;
                    int v = byte_mode ? (int)mask[t] : ((const int*)mask)[t];
                    s_rvalid[r] = (v != 0);
                }
            }
            __syncthreads();

            for (int d = tid; d < D; d += TPB) {
                float s = 0.f;
                for (int r = 0; r < nr; r++)
                    if (s_rvalid[r])
                        s += protos[(size_t)(rs + r) * D + d] * s_inv[r];
                atomicAdd(&g.svec[d], s);
            }
            if (tid == 0) {
                float ds = 0.f;
                for (int r = 0; r < nr; r++) if (s_rvalid[r]) ds += s_rn2[r];
                atomicAdd(&g.diag, ds);
            }

            const int npr = nr * (nr - 1) / 2;
            float local = 0.f;
            for (int k = warp; k < npr; k += nwarp) {
                int i = 0, rem = k;
                while (rem >= nr - 1 - i) { rem -= nr - 1 - i; i++; }
                int j = i + 1 + rem;
                const float* ri = protos + (size_t)(rs + i) * D;
                const float* rj = protos + (size_t)(rs + j) * D;
                float dot = 0.f;
                for (int d = lane; d < D; d += 32) dot += ri[d] * rj[d];
                #pragma unroll
                for (int o = 16; o; o >>= 1) dot += __shfl_xor_sync(0xFFFFFFFFu, dot, o);
                if (lane == 0)
                    local += 2.0f * fmaxf(dot * s_inv[i] * s_inv[j] - 0.5f, 0.f);
            }
            if (lane == 0 && local != 0.f) atomicAdd(&s_pair, local);
            __syncthreads();
        }

        if (tid == 0) {
            int cnt = pidx[2 * c + 1] - pidx[2 * c];
            if (cnt > 1) {
                float npf = (float)cnt * (float)(cnt - 1);
                atomicAdd(&g.div_sum, s_pair / fmaxf(npf, 1.0f));
                atomicAdd(&g.ndv, 1.0f);
            }
        }
        __syncthreads();
    } else {
        // =================== streaming min warps ===========================
        const int CP = C * P;
        const int gw = ((int)blockIdx.x - C) * nwarp + warp;
        const int stride = NMIN * nwarp;

        int okf = 1;
        for (int c = tid; c < C; c += TPB)
            okf &= ((pidx[2 * c + 1] - pidx[2 * c]) >= P);
        okf = __syncthreads_and(okf) & fast_ok;

        if (okf) {
            const int n4 = CP >> 2;
            const float NI = -inff();
            for (int b = gw; b < B; b += stride) {
                const float4* s4 = (const float4*)(sims + (size_t)b * CP);
                const int lbl = labels[b];

                // batch ALL 8 LDG.128 first (x[] live) to maximize MLP
                float4 x[8];
                #pragma unroll
                for (int k = 0; k < 8; k++) {
                    int vi = lane + 32 * k;
                    x[k] = make_float4(NI, NI, NI, NI);
                    if (vi < n4) x[k] = s4[vi];
                }

                const int lo = lbl * P, hi = lo + P;
                const int viL = lo >> 2, viH = (hi - 1) >> 2;
                float oth = NI;
                #pragma unroll
                for (int k = 0; k < 8; k++) {
                    int vi = lane + 32 * k;
                    float m4 = fmaxf(fmaxf(x[k].x, x[k].y), fmaxf(x[k].z, x[k].w));
                    if (vi < viL || vi > viH) oth = fmaxf(oth, m4);
                }

                // boundary region [4*viL, 4*viL+16): lanes 0..15, L1 hits
                float own = NI;
                const int bidx = 4 * viL + lane;
                if (lane < 16 && bidx < CP) {
                    float bv = sims[(size_t)b * CP + bidx];
                    if (bidx >= lo && bidx < hi) own = bv;
                    else if (bidx <= 4 * viH + 3) oth = fmaxf(oth, bv);
                }

                #pragma unroll
                for (int o = 16; o; o >>= 1) {
                    own = fmaxf(own, __shfl_xor_sync(0xFFFFFFFFu, own, o));
                    oth = fmaxf(oth, __shfl_xor_sync(0xFFFFFFFFu, oth, o));
                }
                if (lane == 0) {
                    float ownd = 1.0f - own;
                    float sep  = fmaxf(MARGIN - (1.0f - oth), 0.0f);
                    atomicAdd(&g.cls_n[lbl],   1.0f);
                    atomicAdd(&g.cls_sum[lbl], ownd);
                    atomicAdd(&g.sep_sum[lbl], sep);
                }
            }
        } else {
            for (int b = gw; b < B; b += stride) {
                const float* src = sims + (size_t)b * CP;
                const int lbl = labels[b];
                float ownmax = -inff(), othermax = -inff();
                for (int c = lane; c < C; c += 32) {
                    int cnt = pidx[2 * c + 1] - pidx[2 * c];
                    if (cnt > P) cnt = P;
                    float m = -inff();
                    const float* pr = src + c * P;
                    for (int p = 0; p < cnt; p++) m = fmaxf(m, pr[p]);
                    if (c == lbl) ownmax = m;
                    else          othermax = fmaxf(othermax, m);
                }
                #pragma unroll
                for (int o = 16; o; o >>= 1) {
                    ownmax   = fmaxf(ownmax,   __shfl_xor_sync(0xFFFFFFFFu, ownmax,   o));
                    othermax = fmaxf(othermax, __shfl_xor_sync(0xFFFFFFFFu, othermax, o));
                }
                if (lane == 0) {
                    float own   = 1.0f - ownmax;
                    float other = 1.0f - othermax;
                    float sep   = fmaxf(MARGIN - other, 0.0f);
                    atomicAdd(&g.cls_n[lbl],   1.0f);
                    atomicAdd(&g.cls_sum[lbl], own);
                    atomicAdd(&g.sep_sum[lbl], sep);
                }
            }
        }
        __syncthreads();
    }

    // =================== last-block finalize ===============================
    __threadfence();
    __shared__ unsigned int s_ord;
    if (tid == 0) s_ord = atomicAdd(&g.counter, 1u);
    __syncthreads();
    if (s_ord != (unsigned)(C + NMIN - 1)) return;
    __threadfence();

    int bad2 = 0;
    {
        const int* mi = (const int*)mask;
        const int n = T >> 2;
        for (int i = tid; i < n; i += TPB) {
            int v = mi[i];
            bad2 |= (v != 0 && v != 1);
        }
    }
    const int byte_mode = __syncthreads_or(bad2);

    __shared__ float red[TPB];
    float ca = 0.f, sa = 0.f, nv = 0.f;
    for (int c = tid; c < C; c += TPB) {
        float n = g.cls_n[c];
        if (n > 0.f) {
            nv += 1.f;
            float nm = fmaxf(n, 1.f);
            ca += (1.0f / sqrtf(n + 1e-6f)) * (g.cls_sum[c] / nm);
            sa += g.sep_sum[c] / nm;
        }
    }
    float sn = 0.f;
    for (int d = tid; d < D; d += TPB) { float v = g.svec[d]; sn += v * v; }
    float vc = 0.f;
    for (int t = tid; t < T; t += TPB) {
        int v = byte_mode ? (int)mask[t] : ((const int*)mask)[t];
        vc += (v != 0) ? 1.f : 0.f;
    }

    float vals[5] = {ca, sa, nv, sn, vc};
    #pragma unroll
    for (int k = 0; k < 5; k++) {
        red[tid] = vals[k];
        __syncthreads();
        for (int s = TPB >> 1; s; s >>= 1) {
            if (tid < s) red[tid] += red[tid + s];
            __syncthreads();
        }
        vals[k] = red[0];
        __syncthreads();
    }

    if (tid == 0) {
        float nvalid  = fmaxf(vals[2], 1.f);
        float cluster = vals[0] / nvalid * CLST_SCALE;
        float sep     = vals[1] / nvalid * SEP_SCALE;
        float divl    = g.div_sum / fmaxf(g.ndv, 1.f) * DIV_SCALE;
        float V       = vals[4];
        float nvp     = fmaxf(V * V - V, 1.f);
        float contr   = (vals[3] - g.diag) / nvp * CONTRASTIVE_SCALE;
        out[0] = cluster;
        out[1] = sep;
        out[2] = divl;
        out[3] = contr;
        out[4] = cluster + sep + divl + contr;
    }
}

extern "C" void kernel_launch(void* const* d_in, const int* in_sizes, int n_in,
                              void* d_out, int out_size) {
    const float* sims   = (const float*)d_in[0];
    const int*   labels = (const int*)  d_in[1];
    const float* protos = (const float*)d_in[2];
    const int*   pidx   = (const int*)  d_in[3];
    const unsigned char* mask = (const unsigned char*)d_in[4];

    const int B = in_sizes[1];
    const int C = in_sizes[3] / 2;
    const int T = in_sizes[4];
    const int D = in_sizes[2] / T;
    const int P = in_sizes[0] / (B * C);
    float* out = (float*)d_out;

    void* gp = nullptr;
    cudaGetSymbolAddress(&gp, g);
    cudaMemsetAsync(gp, 0, sizeof(Scratch), 0);

    const int CP = C * P;
    const int fast_ok = (((CP & 3) == 0) && (CP <= 1024) && (P <= 13)) ? 1 : 0;

    // 2048 min blocks -> 8192 warps -> 2 rows/warp; residency-saturating grid
    const int NMIN = 2048;
    fused_kernel<<<C + NMIN, TPB, 0>>>(sims, labels, protos, pidx, mask,
                                       out, B, C, P, T, D, NMIN, fast_ok);
}